// round 8
// baseline (speedup 1.0000x reference)
#include <cuda_runtime.h>
#include <mma.h>
#include <math.h>
#include <stdint.h>

using namespace nvcuda;

#define BATCH 4
#define SEQ   4096
#define DIMC  1024
#define NHEAD 16
#define HDIM  64
#define NWIN  16
#define BLKT  256
#define MTOK  (BATCH*SEQ)
#define QCH   64
#define ATTN_SCALE 0.125f
#define SLD 264

#define BM 128
#define BN 128
#define BK 32
#define STAGES 2
#define LDA 36

// scratch: xr, q, k, v, go (5 x 16M) + 4 rounded weights
__device__ float g_scratch[5ull * MTOK * DIMC + 4ull * DIMC * DIMC];

// ---------------- helpers ----------------
__device__ __forceinline__ void cp_async16(void* smem, const void* gmem) {
    unsigned s = (unsigned)__cvta_generic_to_shared(smem);
    asm volatile("cp.async.cg.shared.global [%0], [%1], 16;\n" :: "r"(s), "l"(gmem));
}
__device__ __forceinline__ void cp_commit() {
    asm volatile("cp.async.commit_group;\n");
}
template<int N> __device__ __forceinline__ void cp_wait() {
    asm volatile("cp.async.wait_group %0;\n" :: "n"(N));
}
__device__ __forceinline__ float round_tf32(float x) {
    uint32_t u;
    asm("cvt.rna.tf32.f32 %0, %1;" : "=r"(u) : "f"(x));
    return __uint_as_float(u);
}

// ---------------------------------------------------------------------------
// Merged tf32-RN rounding prepass: one launch, blockIdx.z selects tensor.
// ---------------------------------------------------------------------------
__global__ void round_all_kernel(
    const float4* __restrict__ x,  float4* __restrict__ xr,
    const float4* __restrict__ w0, float4* __restrict__ w0r,
    const float4* __restrict__ w1, float4* __restrict__ w1r,
    const float4* __restrict__ w2, float4* __restrict__ w2r,
    const float4* __restrict__ w3, float4* __restrict__ w3r)
{
    const float4* src; float4* dst; int n4;
    switch (blockIdx.z) {
        case 0:  src = x;  dst = xr;  n4 = MTOK * DIMC / 4; break;
        case 1:  src = w0; dst = w0r; n4 = DIMC * DIMC / 4; break;
        case 2:  src = w1; dst = w1r; n4 = DIMC * DIMC / 4; break;
        case 3:  src = w2; dst = w2r; n4 = DIMC * DIMC / 4; break;
        default: src = w3; dst = w3r; n4 = DIMC * DIMC / 4; break;
    }
    for (int i = blockIdx.x * blockDim.x + threadIdx.x; i < n4;
         i += gridDim.x * blockDim.x) {
        float4 v = src[i];
        v.x = round_tf32(v.x); v.y = round_tf32(v.y);
        v.z = round_tf32(v.z); v.w = round_tf32(v.w);
        dst[i] = v;
    }
}

// ---------------------------------------------------------------------------
// C[M,1024] = A[M,1024] @ W[1024,1024]^T + bias.  A, W pre-rounded to tf32.
// 128x128 CTA tile, 4 warps, warp tile 64x64, BK=32, 2-stage cp.async
// (wait-all at top: the only pending group IS the stage we're about to read),
// one sync per K-tile, 3 CTAs/SM (12 warps/SM for latency cover).
// ---------------------------------------------------------------------------
__global__ __launch_bounds__(128, 3) void gemm3_tf32(
    const float* __restrict__ A,
    const float* __restrict__ W0, const float* __restrict__ b0, float* __restrict__ C0,
    const float* __restrict__ W1, const float* __restrict__ b1, float* __restrict__ C1,
    const float* __restrict__ W2, const float* __restrict__ b2, float* __restrict__ C2,
    int roundOut)
{
    extern __shared__ float sm[];
    const float* Bw; const float* bias; float* C;
    if (blockIdx.z == 0)      { Bw = W0; bias = b0; C = C0; }
    else if (blockIdx.z == 1) { Bw = W1; bias = b1; C = C1; }
    else                      { Bw = W2; bias = b2; C = C2; }

    const int K = DIMC, N = DIMC;
    const int tid  = threadIdx.x;
    const int warp = tid >> 5;       // 0..3
    const int lane = tid & 31;
    const int wm = warp & 1;         // 2 warps along M
    const int wn = warp >> 1;        // 2 warps along N
    const int rowBase = blockIdx.y * BM;
    const int colBase = blockIdx.x * BN;

    const int stageF = BM * LDA;
    auto As = [&](int s) { return sm + (size_t)s * 2 * stageF; };
    auto Bs = [&](int s) { return sm + (size_t)s * 2 * stageF + stageF; };

    const int lr = tid >> 3;          // 0..15
    const int lc = (tid & 7) * 4;     // 0..28

    auto loadStage = [&](int s, int kt) {
        float* as = As(s); float* bs = Bs(s);
        int k0 = kt * BK;
        #pragma unroll
        for (int j = 0; j < 8; j++) {
            int r = lr + j * 16;
            cp_async16(&as[r * LDA + lc], &A [(size_t)(rowBase + r) * K + k0 + lc]);
            cp_async16(&bs[r * LDA + lc], &Bw[(size_t)(colBase + r) * K + k0 + lc]);
        }
        cp_commit();
    };

    wmma::fragment<wmma::accumulator,16,16,8,float> acc[4][4];
    #pragma unroll
    for (int i = 0; i < 4; i++)
        #pragma unroll
        for (int j = 0; j < 4; j++)
            wmma::fill_fragment(acc[i][j], 0.0f);

    const int NT = K / BK;            // 32
    loadStage(0, 0);

    for (int kt = 0; kt < NT; kt++) {
        // Wait ALL pending groups: the group for stage kt&1 (issued at kt-1,
        // or the prologue for kt=0) is the only one in flight. cp_wait<1>
        // here would return with it still incomplete -> silent corruption.
        cp_wait<0>();
        __syncthreads();
        // slot (kt+1)&1 was computed at kt-1; the sync above covers it.
        // This load overlaps with compute of stage kt&1 below.
        if (kt + 1 < NT) loadStage((kt + 1) & 1, kt + 1);

        const float* as = As(kt & 1);
        const float* bs = Bs(kt & 1);
        #pragma unroll
        for (int kk = 0; kk < BK; kk += 8) {
            wmma::fragment<wmma::matrix_b,16,16,8,wmma::precision::tf32,wmma::col_major> bf[4];
            #pragma unroll
            for (int j = 0; j < 4; j++)
                wmma::load_matrix_sync(bf[j], bs + (wn*64 + j*16) * LDA + kk, LDA);
            #pragma unroll
            for (int i = 0; i < 4; i++) {
                wmma::fragment<wmma::matrix_a,16,16,8,wmma::precision::tf32,wmma::row_major> af;
                wmma::load_matrix_sync(af, as + (wm*64 + i*16) * LDA + kk, LDA);
                #pragma unroll
                for (int j = 0; j < 4; j++)
                    wmma::mma_sync(acc[i][j], af, bf[j], acc[i][j]);
            }
        }
    }
    __syncthreads();

    // epilogue: stage 16x16 tiles through smem, add bias, vector store
    float* wstg = sm + warp * 352;
    #pragma unroll
    for (int i = 0; i < 4; i++) {
        #pragma unroll
        for (int j = 0; j < 4; j++) {
            wmma::store_matrix_sync(wstg, acc[i][j], 20, wmma::mem_row_major);
            __syncwarp();
            int r0 = rowBase + wm*64 + i*16;
            int c0 = colBase + wn*64 + j*16;
            int r  = lane >> 1;
            int cc = (lane & 1) * 8;
            float o[8];
            #pragma unroll
            for (int t = 0; t < 8; t++)
                o[t] = wstg[r*20 + cc + t] + __ldg(&bias[c0 + cc + t]);
            if (roundOut) {
                #pragma unroll
                for (int t = 0; t < 8; t++) o[t] = round_tf32(o[t]);
            }
            *(float4*)&C[(size_t)(r0 + r) * N + c0 + cc]     = *(float4*)&o[0];
            *(float4*)&C[(size_t)(r0 + r) * N + c0 + cc + 4] = *(float4*)&o[4];
            __syncwarp();
        }
    }
}

// ---------------------------------------------------------------------------
// Block-local attention. One CTA per window, 512 threads. q,k,v pre-rounded
// tf32. P rounded in softmax; O rounded in epilogue (feeds tf32 Wo GEMM).
// ---------------------------------------------------------------------------
__global__ __launch_bounds__(512) void attn_kernel(
    const float* __restrict__ q, const float* __restrict__ k,
    const float* __restrict__ v, float* __restrict__ o,
    float* __restrict__ attnp)
{
    extern __shared__ float sm[];
    float* Ks = sm;
    float* Vs = Ks + 256*64;
    float* Qs = Vs + 256*64;
    float* Ss = Qs + 64*64;

    const int tid  = threadIdx.x;
    const int warp = tid >> 5;
    const int wm = warp >> 2;
    const int wn = warp & 3;

    const int bhw = blockIdx.x;
    const int w = bhw & 15;
    const int h = (bhw >> 4) & 15;
    const int b = bhw >> 8;

    const size_t tokBase = (size_t)b * SEQ + (size_t)w * BLKT;
    const int    colBase = h * HDIM;

    const float* Kg = k + tokBase * DIMC + colBase;
    const float* Vg = v + tokBase * DIMC + colBase;
    const float* Qg = q + tokBase * DIMC + colBase;

    #pragma unroll
    for (int j = 0; j < 8; j++) {
        int i = tid + j * 512;
        int r = i >> 4, c = (i & 15) * 4;
        cp_async16(&Ks[r*64 + c], Kg + (size_t)r * DIMC + c);
        cp_async16(&Vs[r*64 + c], Vg + (size_t)r * DIMC + c);
    }
    #pragma unroll
    for (int j = 0; j < 2; j++) {
        int i = tid + j * 512;
        int r = i >> 4, c = (i & 15) * 4;
        cp_async16(&Qs[r*64 + c], Qg + (size_t)r * DIMC + c);
    }
    cp_commit();
    cp_wait<0>();
    __syncthreads();

    for (int qc = 0; qc < 4; qc++) {
        // ---- S = Q @ K^T ----
        {
            wmma::fragment<wmma::accumulator,16,16,8,float> sacc[4];
            #pragma unroll
            for (int j = 0; j < 4; j++) wmma::fill_fragment(sacc[j], 0.0f);
            #pragma unroll
            for (int d0 = 0; d0 < HDIM; d0 += 8) {
                wmma::fragment<wmma::matrix_a,16,16,8,wmma::precision::tf32,wmma::row_major> af;
                wmma::load_matrix_sync(af, Qs + (wm*16)*HDIM + d0, HDIM);
                #pragma unroll
                for (int j = 0; j < 4; j++) {
                    wmma::fragment<wmma::matrix_b,16,16,8,wmma::precision::tf32,wmma::col_major> bf;
                    wmma::load_matrix_sync(bf, Ks + (size_t)(wn*64 + j*16)*HDIM + d0, HDIM);
                    wmma::mma_sync(sacc[j], af, bf, sacc[j]);
                }
            }
            #pragma unroll
            for (int j = 0; j < 4; j++)
                wmma::store_matrix_sync(Ss + (wm*16)*SLD + wn*64 + j*16, sacc[j],
                                        SLD, wmma::mem_row_major);
        }
        __syncthreads();

        if (qc < 3) {
            const float* Qn = Qg + (size_t)(qc + 1) * QCH * DIMC;
            #pragma unroll
            for (int j = 0; j < 2; j++) {
                int i = tid + j * 512;
                int r = i >> 4, c = (i & 15) * 4;
                cp_async16(&Qs[r*64 + c], Qn + (size_t)r * DIMC + c);
            }
            cp_commit();
        }

        // ---- softmax ----
        {
            const int row  = tid >> 3;
            const int part = tid & 7;
            float* srow = Ss + row * SLD;
            float mx = -1e30f;
            #pragma unroll
            for (int j = 0; j < 32; j++) mx = fmaxf(mx, srow[j*8 + part]);
            mx = fmaxf(mx, __shfl_xor_sync(0xffffffffu, mx, 1));
            mx = fmaxf(mx, __shfl_xor_sync(0xffffffffu, mx, 2));
            mx = fmaxf(mx, __shfl_xor_sync(0xffffffffu, mx, 4));
            float sum = 0.0f;
            #pragma unroll
            for (int j = 0; j < 32; j++) {
                float e = __expf((srow[j*8 + part] - mx) * ATTN_SCALE);
                srow[j*8 + part] = e;
                sum += e;
            }
            sum += __shfl_xor_sync(0xffffffffu, sum, 1);
            sum += __shfl_xor_sync(0xffffffffu, sum, 2);
            sum += __shfl_xor_sync(0xffffffffu, sum, 4);
            const float inv = 1.0f / sum;
            if (attnp) {
                float* arow = attnp + ((((size_t)b*NHEAD + h)*NWIN + w)*BLKT
                                       + qc*QCH + row) * BLKT;
                #pragma unroll
                for (int j = 0; j < 32; j++) {
                    float p = srow[j*8 + part] * inv;
                    __stcs(&arow[j*8 + part], p);
                    srow[j*8 + part] = round_tf32(p);
                }
            } else {
                #pragma unroll
                for (int j = 0; j < 32; j++)
                    srow[j*8 + part] = round_tf32(srow[j*8 + part] * inv);
            }
        }
        __syncthreads();

        // ---- O = P @ V (output rounded to tf32 for the Wo GEMM) ----
        {
            wmma::fragment<wmma::accumulator,16,16,8,float> oacc;
            wmma::fill_fragment(oacc, 0.0f);
            #pragma unroll 8
            for (int k0 = 0; k0 < BLKT; k0 += 8) {
                wmma::fragment<wmma::matrix_a,16,16,8,wmma::precision::tf32,wmma::row_major> af;
                wmma::load_matrix_sync(af, Ss + (wm*16)*SLD + k0, SLD);
                wmma::fragment<wmma::matrix_b,16,16,8,wmma::precision::tf32,wmma::row_major> bf;
                wmma::load_matrix_sync(bf, Vs + (size_t)k0*HDIM + wn*16, HDIM);
                wmma::mma_sync(oacc, af, bf, oacc);
            }
            #pragma unroll
            for (int e = 0; e < oacc.num_elements; e++)
                oacc.x[e] = round_tf32(oacc.x[e]);
            float* optr = o + (tokBase + (size_t)qc*QCH + wm*16) * DIMC
                            + colBase + wn*16;
            wmma::store_matrix_sync(optr, oacc, DIMC, wmma::mem_row_major);
        }

        if (qc < 3) cp_wait<0>();
        __syncthreads();
    }
}

// ---------------------------------------------------------------------------
extern "C" void kernel_launch(void* const* d_in, const int* in_sizes, int n_in,
                              void* d_out, int out_size)
{
    const float* x  = (const float*)d_in[0];
    const float* Wq = (const float*)d_in[1];
    const float* bq = (const float*)d_in[2];
    const float* Wk = (const float*)d_in[3];
    const float* bk = (const float*)d_in[4];
    const float* Wv = (const float*)d_in[5];
    const float* bv = (const float*)d_in[6];
    const float* Wo = (const float*)d_in[7];
    const float* bo = (const float*)d_in[8];

    float* out = (float*)d_out;
    const size_t out_elems = (size_t)MTOK * DIMC;
    float* attnp = ((size_t)out_size > out_elems) ? (out + out_elems) : nullptr;

    float* scratch = nullptr;
    cudaGetSymbolAddress((void**)&scratch, g_scratch);
    float* xr = scratch;
    float* gq = xr + out_elems;
    float* gk = gq + out_elems;
    float* gv = gk + out_elems;
    float* go = gv + out_elems;
    float* wr = go + out_elems;
    const size_t wsz = (size_t)DIMC * DIMC;
    float* wrq = wr;
    float* wrk = wr + wsz;
    float* wrv = wr + 2*wsz;
    float* wro = wr + 3*wsz;

    // single merged rounding launch
    {
        dim3 rg(256, 1, 5);
        round_all_kernel<<<rg, 256>>>(
            (const float4*)x,  (float4*)xr,
            (const float4*)Wq, (float4*)wrq,
            (const float4*)Wk, (float4*)wrk,
            (const float4*)Wv, (float4*)wrv,
            (const float4*)Wo, (float4*)wro);
    }

    const size_t gemm_smem = (size_t)STAGES * 2 * BM * LDA * sizeof(float); // 73728
    cudaFuncSetAttribute(gemm3_tf32, cudaFuncAttributeMaxDynamicSharedMemorySize, (int)gemm_smem);

    dim3 gg(DIMC / BN, MTOK / BM, 3);
    gemm3_tf32<<<gg, 128, gemm_smem>>>(xr, wrq, bq, gq, wrk, bk, gk, wrv, bv, gv, 1);

    const size_t attn_smem = (size_t)(256*64*2 + 64*64 + 64*SLD) * sizeof(float);
    cudaFuncSetAttribute(attn_kernel, cudaFuncAttributeMaxDynamicSharedMemorySize, (int)attn_smem);
    attn_kernel<<<BATCH*NHEAD*NWIN, 512, attn_smem>>>(gq, gk, gv, go, attnp);

    dim3 go_grid(DIMC / BN, MTOK / BM, 1);
    gemm3_tf32<<<go_grid, 128, gemm_smem>>>(go, wro, bo, out, wro, bo, out, wro, bo, out, 0);
}

// round 9
// speedup vs baseline: 3.9429x; 3.9429x over previous
#include <cuda_runtime.h>
#include <cuda_fp16.h>
#include <mma.h>
#include <math.h>
#include <stdint.h>

using namespace nvcuda;

#define BATCH 4
#define SEQ   4096
#define DIMC  1024
#define NHEAD 16
#define HDIM  64
#define NWIN  16
#define BLKT  256
#define MTOK  (BATCH*SEQ)
#define QCH   64
#define ATTN_SCALE 0.125f
#define SLD 264          // fp32 score row stride
#define PLD 280          // fp16 P row stride (140 words -> 12r mod 32, conflict-free LDSM)

#define BM 128
#define BN 128
#define BKH 64           // K elements per tile (half): 128B rows
#define LDH 72           // half stride (144B rows -> 4r mod 32, conflict-free LDSM)
#define NT  (DIMC / BKH) // 16

// scratch (halves): xh, qh, kh, vh, goh (5 x 16M half) + 4 weights (1M half each)
__device__ __half g_scratch_h[5ull * MTOK * DIMC + 4ull * DIMC * DIMC];

// ---------------- helpers ----------------
__device__ __forceinline__ void cp_async16(void* smem, const void* gmem) {
    unsigned s = (unsigned)__cvta_generic_to_shared(smem);
    asm volatile("cp.async.cg.shared.global [%0], [%1], 16;\n" :: "r"(s), "l"(gmem));
}
__device__ __forceinline__ void cp_commit() {
    asm volatile("cp.async.commit_group;\n");
}
template<int N> __device__ __forceinline__ void cp_wait() {
    asm volatile("cp.async.wait_group %0;\n" :: "n"(N));
}

// ---------------------------------------------------------------------------
// f32 -> f16 (RN) conversion prepass: one launch, blockIdx.z selects tensor.
// ---------------------------------------------------------------------------
__global__ void conv_half_kernel(
    const float4* __restrict__ x,  __half* __restrict__ xh,
    const float4* __restrict__ w0, __half* __restrict__ w0h,
    const float4* __restrict__ w1, __half* __restrict__ w1h,
    const float4* __restrict__ w2, __half* __restrict__ w2h,
    const float4* __restrict__ w3, __half* __restrict__ w3h)
{
    const float4* src; __half* dst; int n4;
    switch (blockIdx.z) {
        case 0:  src = x;  dst = xh;  n4 = MTOK * DIMC / 4; break;
        case 1:  src = w0; dst = w0h; n4 = DIMC * DIMC / 4; break;
        case 2:  src = w1; dst = w1h; n4 = DIMC * DIMC / 4; break;
        case 3:  src = w2; dst = w2h; n4 = DIMC * DIMC / 4; break;
        default: src = w3; dst = w3h; n4 = DIMC * DIMC / 4; break;
    }
    for (int i = blockIdx.x * blockDim.x + threadIdx.x; i < n4;
         i += gridDim.x * blockDim.x) {
        float4 v = src[i];
        __half2 a = __floats2half2_rn(v.x, v.y);
        __half2 b = __floats2half2_rn(v.z, v.w);
        uint2 o;
        o.x = *(const unsigned*)&a;
        o.y = *(const unsigned*)&b;
        *(uint2*)(dst + 4ull * i) = o;
    }
}

// ---------------------------------------------------------------------------
// C[M,1024] = A[M,1024] @ W[1024,1024]^T + bias.  A, W fp16, fp32 accumulate.
// 128x128 CTA tile, 4 warps (warp tile 64x64), BK=64 halves, 2-stage cp.async
// (wait-all at top -- the only pending group is the stage about to be read),
// one sync per K-tile, 3 CTAs/SM. halfOut: C is __half; else C is float.
// ---------------------------------------------------------------------------
__global__ __launch_bounds__(128, 3) void gemm3_f16(
    const __half* __restrict__ A,
    const __half* __restrict__ W0, const float* __restrict__ b0, void* __restrict__ C0,
    const __half* __restrict__ W1, const float* __restrict__ b1, void* __restrict__ C1,
    const __half* __restrict__ W2, const float* __restrict__ b2, void* __restrict__ C2,
    int halfOut)
{
    extern __shared__ __half smh[];
    const __half* Bw; const float* bias; void* C;
    if (blockIdx.z == 0)      { Bw = W0; bias = b0; C = C0; }
    else if (blockIdx.z == 1) { Bw = W1; bias = b1; C = C1; }
    else                      { Bw = W2; bias = b2; C = C2; }

    const int K = DIMC, N = DIMC;
    const int tid  = threadIdx.x;
    const int warp = tid >> 5;       // 0..3
    const int lane = tid & 31;
    const int wm = warp & 1;         // 2 warps along M
    const int wn = warp >> 1;        // 2 warps along N
    const int rowBase = blockIdx.y * BM;
    const int colBase = blockIdx.x * BN;

    const int stageH = BM * LDH;     // halves per tile
    auto As = [&](int s) { return smh + (size_t)s * 2 * stageH; };
    auto Bs = [&](int s) { return smh + (size_t)s * 2 * stageH + stageH; };

    const int lr = tid >> 3;          // 0..15
    const int lc = (tid & 7) * 8;     // halves (16B chunks)

    auto loadStage = [&](int s, int kt) {
        __half* as = As(s); __half* bs = Bs(s);
        int k0 = kt * BKH;
        #pragma unroll
        for (int j = 0; j < 8; j++) {
            int r = lr + j * 16;
            cp_async16(&as[r * LDH + lc], &A [(size_t)(rowBase + r) * K + k0 + lc]);
            cp_async16(&bs[r * LDH + lc], &Bw[(size_t)(colBase + r) * K + k0 + lc]);
        }
        cp_commit();
    };

    wmma::fragment<wmma::accumulator,16,16,16,float> acc[4][4];
    #pragma unroll
    for (int i = 0; i < 4; i++)
        #pragma unroll
        for (int j = 0; j < 4; j++)
            wmma::fill_fragment(acc[i][j], 0.0f);

    loadStage(0, 0);

    for (int kt = 0; kt < NT; kt++) {
        cp_wait<0>();                     // wait-all: sole pending group is stage kt&1
        __syncthreads();
        if (kt + 1 < NT) loadStage((kt + 1) & 1, kt + 1);   // overlaps compute below

        const __half* as = As(kt & 1);
        const __half* bs = Bs(kt & 1);
        #pragma unroll
        for (int kk = 0; kk < BKH; kk += 16) {
            wmma::fragment<wmma::matrix_b,16,16,16,__half,wmma::col_major> bf[4];
            #pragma unroll
            for (int j = 0; j < 4; j++)
                wmma::load_matrix_sync(bf[j], bs + (wn*64 + j*16) * LDH + kk, LDH);
            #pragma unroll
            for (int i = 0; i < 4; i++) {
                wmma::fragment<wmma::matrix_a,16,16,16,__half,wmma::row_major> af;
                wmma::load_matrix_sync(af, as + (wm*64 + i*16) * LDH + kk, LDH);
                #pragma unroll
                for (int j = 0; j < 4; j++)
                    wmma::mma_sync(acc[i][j], af, bf[j], acc[i][j]);
            }
        }
    }
    __syncthreads();

    // epilogue: stage 16x16 fp32 tiles through smem, add bias, store f16 or f32
    float* wstg = (float*)smh + warp * 352;
    #pragma unroll
    for (int i = 0; i < 4; i++) {
        #pragma unroll
        for (int j = 0; j < 4; j++) {
            wmma::store_matrix_sync(wstg, acc[i][j], 20, wmma::mem_row_major);
            __syncwarp();
            int r0 = rowBase + wm*64 + i*16;
            int c0 = colBase + wn*64 + j*16;
            int r  = lane >> 1;
            int cc = (lane & 1) * 8;
            float o[8];
            #pragma unroll
            for (int t = 0; t < 8; t++)
                o[t] = wstg[r*20 + cc + t] + __ldg(&bias[c0 + cc + t]);
            if (halfOut) {
                __half h[8];
                #pragma unroll
                for (int t = 0; t < 8; t++) h[t] = __float2half_rn(o[t]);
                *(uint4*)&((__half*)C)[(size_t)(r0 + r) * N + c0 + cc] = *(uint4*)h;
            } else {
                *(float4*)&((float*)C)[(size_t)(r0 + r) * N + c0 + cc]     = *(float4*)&o[0];
                *(float4*)&((float*)C)[(size_t)(r0 + r) * N + c0 + cc + 4] = *(float4*)&o[4];
            }
            __syncwarp();
        }
    }
}

// ---------------------------------------------------------------------------
// Block-local attention, fp16 operands / fp32 softmax+attn output.
// One CTA per window, 512 threads.
// smem layout (bytes):
//   Ks half [256][LDH]  @ 0        (36864)
//   Vs half [256][LDH]  @ 36864    (36864)
//   Qs half [64][LDH]   @ 73728    (9216)
//   Ss f32  [64][SLD]   @ 82944    (67584)   (also reused as epilogue staging)
//   Ps half [64][PLD]   @ 150528   (35840)   total 186368
// ---------------------------------------------------------------------------
#define ATTN_SMEM 186368

__global__ __launch_bounds__(512) void attn_kernel(
    const __half* __restrict__ q, const __half* __restrict__ k,
    const __half* __restrict__ v, __half* __restrict__ o,
    float* __restrict__ attnp)
{
    extern __shared__ char smraw[];
    __half* Ks = (__half*)smraw;
    __half* Vs = (__half*)(smraw + 36864);
    __half* Qs = (__half*)(smraw + 73728);
    float*  Ss = (float*) (smraw + 82944);
    __half* Ps = (__half*)(smraw + 150528);

    const int tid  = threadIdx.x;
    const int warp = tid >> 5;
    const int wm = warp >> 2;        // 0..3 : 16-row group
    const int wn = warp & 3;         // 0..3 : 16-col group

    const int bhw = blockIdx.x;
    const int w = bhw & 15;
    const int h = (bhw >> 4) & 15;
    const int b = bhw >> 8;

    const size_t tokBase = (size_t)b * SEQ + (size_t)w * BLKT;
    const int    colBase = h * HDIM;

    const __half* Kg = k + tokBase * DIMC + colBase;
    const __half* Vg = v + tokBase * DIMC + colBase;
    const __half* Qg = q + tokBase * DIMC + colBase;

    // K,V: 256 rows x 8 chunks(16B) each; Q: 64 rows x 8 chunks
    #pragma unroll
    for (int j = 0; j < 4; j++) {
        int i = tid + j * 512;            // 0..2047
        int r = i >> 3, u = (i & 7) * 8;
        cp_async16(&Ks[r*LDH + u], Kg + (size_t)r * DIMC + u);
        cp_async16(&Vs[r*LDH + u], Vg + (size_t)r * DIMC + u);
    }
    {
        int r = tid >> 3, u = (tid & 7) * 8;
        cp_async16(&Qs[r*LDH + u], Qg + (size_t)r * DIMC + u);
    }
    cp_commit();
    cp_wait<0>();
    __syncthreads();

    for (int qc = 0; qc < 4; qc++) {
        // ---- S = Q @ K^T (fp16 in, fp32 acc) : warp = 16 rows x 64 cols ----
        {
            wmma::fragment<wmma::accumulator,16,16,16,float> sacc[4];
            #pragma unroll
            for (int j = 0; j < 4; j++) wmma::fill_fragment(sacc[j], 0.0f);
            #pragma unroll
            for (int d0 = 0; d0 < HDIM; d0 += 16) {
                wmma::fragment<wmma::matrix_a,16,16,16,__half,wmma::row_major> af;
                wmma::load_matrix_sync(af, Qs + (wm*16)*LDH + d0, LDH);
                #pragma unroll
                for (int j = 0; j < 4; j++) {
                    wmma::fragment<wmma::matrix_b,16,16,16,__half,wmma::col_major> bf;
                    wmma::load_matrix_sync(bf, Ks + (size_t)(wn*64 + j*16)*LDH + d0, LDH);
                    wmma::mma_sync(sacc[j], af, bf, sacc[j]);
                }
            }
            #pragma unroll
            for (int j = 0; j < 4; j++)
                wmma::store_matrix_sync(Ss + (wm*16)*SLD + wn*64 + j*16, sacc[j],
                                        SLD, wmma::mem_row_major);
        }
        __syncthreads();

        // prefetch next Q chunk (Qs free until next qc's QK^T)
        if (qc < 3) {
            const __half* Qn = Qg + (size_t)(qc + 1) * QCH * DIMC;
            int r = tid >> 3, u = (tid & 7) * 8;
            cp_async16(&Qs[r*LDH + u], Qn + (size_t)r * DIMC + u);
            cp_commit();
        }

        // ---- softmax (fp32), write attn (fp32) + P (fp16) ----
        {
            const int row  = tid >> 3;
            const int part = tid & 7;
            float* srow = Ss + row * SLD;
            __half* prow = Ps + row * PLD;
            float mx = -1e30f;
            #pragma unroll
            for (int j = 0; j < 32; j++) mx = fmaxf(mx, srow[j*8 + part]);
            mx = fmaxf(mx, __shfl_xor_sync(0xffffffffu, mx, 1));
            mx = fmaxf(mx, __shfl_xor_sync(0xffffffffu, mx, 2));
            mx = fmaxf(mx, __shfl_xor_sync(0xffffffffu, mx, 4));
            float sum = 0.0f;
            #pragma unroll
            for (int j = 0; j < 32; j++) {
                float e = __expf((srow[j*8 + part] - mx) * ATTN_SCALE);
                srow[j*8 + part] = e;
                sum += e;
            }
            sum += __shfl_xor_sync(0xffffffffu, sum, 1);
            sum += __shfl_xor_sync(0xffffffffu, sum, 2);
            sum += __shfl_xor_sync(0xffffffffu, sum, 4);
            const float inv = 1.0f / sum;
            float* arow = attnp + ((((size_t)b*NHEAD + h)*NWIN + w)*BLKT
                                   + qc*QCH + row) * BLKT;
            #pragma unroll
            for (int j = 0; j < 32; j++) {
                float p = srow[j*8 + part] * inv;
                __stcs(&arow[j*8 + part], p);
                prow[j*8 + part] = __float2half_rn(p);
            }
        }
        __syncthreads();

        // ---- O = P @ V (fp16 in, fp32 acc) : each warp 16x16 tile ----
        {
            wmma::fragment<wmma::accumulator,16,16,16,float> oacc;
            wmma::fill_fragment(oacc, 0.0f);
            #pragma unroll
            for (int k0 = 0; k0 < BLKT; k0 += 16) {
                wmma::fragment<wmma::matrix_a,16,16,16,__half,wmma::row_major> af;
                wmma::load_matrix_sync(af, Ps + (wm*16)*PLD + k0, PLD);
                wmma::fragment<wmma::matrix_b,16,16,16,__half,wmma::row_major> bf;
                wmma::load_matrix_sync(bf, Vs + (size_t)k0*LDH + wn*16, LDH);
                wmma::mma_sync(oacc, af, bf, oacc);
            }
            // stage fp32 -> convert to half -> 16B stores (Ss free during PV)
            float* wstg = Ss + warp * 352;
            wmma::store_matrix_sync(wstg, oacc, 16, wmma::mem_row_major);
            __syncwarp();
            const int lane = tid & 31;
            int r  = lane >> 1;
            int cc = (lane & 1) * 8;
            __half hv[8];
            #pragma unroll
            for (int t = 0; t < 8; t++)
                hv[t] = __float2half_rn(wstg[r*16 + cc + t]);
            __half* optr = o + (tokBase + (size_t)qc*QCH + wm*16 + r) * DIMC
                             + colBase + wn*16 + cc;
            *(uint4*)optr = *(uint4*)hv;
        }

        if (qc < 3) cp_wait<0>();
        __syncthreads();
    }
}

// ---------------------------------------------------------------------------
extern "C" void kernel_launch(void* const* d_in, const int* in_sizes, int n_in,
                              void* d_out, int out_size)
{
    const float* x  = (const float*)d_in[0];
    const float* Wq = (const float*)d_in[1];
    const float* bq = (const float*)d_in[2];
    const float* Wk = (const float*)d_in[3];
    const float* bk = (const float*)d_in[4];
    const float* Wv = (const float*)d_in[5];
    const float* bv = (const float*)d_in[6];
    const float* Wo = (const float*)d_in[7];
    const float* bo = (const float*)d_in[8];

    float* out = (float*)d_out;
    const size_t out_elems = (size_t)MTOK * DIMC;
    float* attnp = out + out_elems;   // harness out_size covers (out, attn)

    __half* scratch = nullptr;
    cudaGetSymbolAddress((void**)&scratch, g_scratch_h);
    __half* xh  = scratch;
    __half* qh  = xh  + out_elems;
    __half* kh  = qh  + out_elems;
    __half* vh  = kh  + out_elems;
    __half* goh = vh  + out_elems;
    __half* wh  = goh + out_elems;
    const size_t wsz = (size_t)DIMC * DIMC;
    __half* whq = wh;
    __half* whk = wh + wsz;
    __half* whv = wh + 2*wsz;
    __half* who = wh + 3*wsz;

    // single merged conversion launch (f32 -> f16 RN)
    {
        dim3 rg(256, 1, 5);
        conv_half_kernel<<<rg, 256>>>(
            (const float4*)x,  xh,
            (const float4*)Wq, whq,
            (const float4*)Wk, whk,
            (const float4*)Wv, whv,
            (const float4*)Wo, who);
    }

    const size_t gemm_smem = 2ull * 2 * BM * LDH * sizeof(__half);  // 73728
    cudaFuncSetAttribute(gemm3_f16, cudaFuncAttributeMaxDynamicSharedMemorySize, (int)gemm_smem);

    dim3 gg(DIMC / BN, MTOK / BM, 3);
    gemm3_f16<<<gg, 128, gemm_smem>>>(xh, whq, bq, qh, whk, bk, kh, whv, bv, vh, 1);

    cudaFuncSetAttribute(attn_kernel, cudaFuncAttributeMaxDynamicSharedMemorySize, ATTN_SMEM);
    attn_kernel<<<BATCH*NHEAD*NWIN, 512, ATTN_SMEM>>>(qh, kh, vh, goh, attnp);

    dim3 go_grid(DIMC / BN, MTOK / BM, 1);
    gemm3_f16<<<go_grid, 128, gemm_smem>>>(goh, who, bo, out, who, bo, out, who, bo, out, 0);
}

// round 10
// speedup vs baseline: 3.9786x; 1.0090x over previous
#include <cuda_runtime.h>
#include <cuda_fp16.h>
#include <mma.h>
#include <math.h>
#include <stdint.h>

using namespace nvcuda;

#define BATCH 4
#define SEQ   4096
#define DIMC  1024
#define NHEAD 16
#define HDIM  64
#define NWIN  16
#define BLKT  256
#define MTOK  (BATCH*SEQ)
#define QCH   64
#define ATTN_SCALE 0.125f
#define SLD 264          // fp32 score row stride
#define PLD 280          // fp16 P row stride

#define BM 128
#define BN 128
#define BKH 64           // K elements per tile (half): 128B rows
#define LDH 72           // half stride (144B rows, conflict-free LDSM)
#define NT  (DIMC / BKH) // 16

// scratch (halves): xh, qh, kh, vh, goh (5 x 16M half) + 4 weights (1M half each)
__device__ __half g_scratch_h[5ull * MTOK * DIMC + 4ull * DIMC * DIMC];

// ---------------- helpers ----------------
__device__ __forceinline__ void cp_async16(void* smem, const void* gmem) {
    unsigned s = (unsigned)__cvta_generic_to_shared(smem);
    asm volatile("cp.async.cg.shared.global [%0], [%1], 16;\n" :: "r"(s), "l"(gmem));
}
__device__ __forceinline__ void cp_commit() {
    asm volatile("cp.async.commit_group;\n");
}
template<int N> __device__ __forceinline__ void cp_wait() {
    asm volatile("cp.async.wait_group %0;\n" :: "n"(N));
}

// fp32 exp via degree-6 exp2 polynomial on the FMA/ALU pipes (no MUFU).
// Valid for v <= ~0 (softmax post-max-subtraction); rel err <= 1.6e-5.
__device__ __forceinline__ float exp_poly(float v) {
    float t = v * 1.4426950408889634f;      // log2(e)
    float fi = floorf(t);
    float f = t - fi;
    float p = 0.0001540353039338f;
    p = fmaf(p, f, 0.0013333558146428f);
    p = fmaf(p, f, 0.0096181291076285f);
    p = fmaf(p, f, 0.0555041086648216f);
    p = fmaf(p, f, 0.2402265069591007f);
    p = fmaf(p, f, 0.6931471805599453f);
    p = fmaf(p, f, 1.0f);
    int ei = (int)fi;
    ei = (ei < -126) ? -126 : ei;
    return p * __int_as_float((ei + 127) << 23);
}

// ---------------------------------------------------------------------------
// f32 -> f16 (RN) conversion prepass: one launch, blockIdx.z selects tensor.
// ---------------------------------------------------------------------------
__global__ void conv_half_kernel(
    const float4* __restrict__ x,  __half* __restrict__ xh,
    const float4* __restrict__ w0, __half* __restrict__ w0h,
    const float4* __restrict__ w1, __half* __restrict__ w1h,
    const float4* __restrict__ w2, __half* __restrict__ w2h,
    const float4* __restrict__ w3, __half* __restrict__ w3h)
{
    const float4* src; __half* dst; int n4;
    switch (blockIdx.z) {
        case 0:  src = x;  dst = xh;  n4 = MTOK * DIMC / 4; break;
        case 1:  src = w0; dst = w0h; n4 = DIMC * DIMC / 4; break;
        case 2:  src = w1; dst = w1h; n4 = DIMC * DIMC / 4; break;
        case 3:  src = w2; dst = w2h; n4 = DIMC * DIMC / 4; break;
        default: src = w3; dst = w3h; n4 = DIMC * DIMC / 4; break;
    }
    for (int i = blockIdx.x * blockDim.x + threadIdx.x; i < n4;
         i += gridDim.x * blockDim.x) {
        float4 v = src[i];
        __half2 a = __floats2half2_rn(v.x, v.y);
        __half2 b = __floats2half2_rn(v.z, v.w);
        uint2 o;
        o.x = *(const unsigned*)&a;
        o.y = *(const unsigned*)&b;
        *(uint2*)(dst + 4ull * i) = o;
    }
}

// ---------------------------------------------------------------------------
// C[M,1024] = A[M,1024] @ W[1024,1024]^T + bias.  fp16 in, fp32 accumulate.
// 128x128 CTA tile, 4 warps (64x64 warp tile), BK=64 halves, 2-stage
// cp.async wait-all pipeline, one sync per K-tile, 3 CTAs/SM.
// ---------------------------------------------------------------------------
__global__ __launch_bounds__(128, 3) void gemm3_f16(
    const __half* __restrict__ A,
    const __half* __restrict__ W0, const float* __restrict__ b0, void* __restrict__ C0,
    const __half* __restrict__ W1, const float* __restrict__ b1, void* __restrict__ C1,
    const __half* __restrict__ W2, const float* __restrict__ b2, void* __restrict__ C2,
    int halfOut)
{
    extern __shared__ __half smh[];
    const __half* Bw; const float* bias; void* C;
    if (blockIdx.z == 0)      { Bw = W0; bias = b0; C = C0; }
    else if (blockIdx.z == 1) { Bw = W1; bias = b1; C = C1; }
    else                      { Bw = W2; bias = b2; C = C2; }

    const int K = DIMC, N = DIMC;
    const int tid  = threadIdx.x;
    const int warp = tid >> 5;
    const int lane = tid & 31;
    const int wm = warp & 1;
    const int wn = warp >> 1;
    const int rowBase = blockIdx.y * BM;
    const int colBase = blockIdx.x * BN;

    const int stageH = BM * LDH;
    auto As = [&](int s) { return smh + (size_t)s * 2 * stageH; };
    auto Bs = [&](int s) { return smh + (size_t)s * 2 * stageH + stageH; };

    const int lr = tid >> 3;
    const int lc = (tid & 7) * 8;

    auto loadStage = [&](int s, int kt) {
        __half* as = As(s); __half* bs = Bs(s);
        int k0 = kt * BKH;
        #pragma unroll
        for (int j = 0; j < 8; j++) {
            int r = lr + j * 16;
            cp_async16(&as[r * LDH + lc], &A [(size_t)(rowBase + r) * K + k0 + lc]);
            cp_async16(&bs[r * LDH + lc], &Bw[(size_t)(colBase + r) * K + k0 + lc]);
        }
        cp_commit();
    };

    wmma::fragment<wmma::accumulator,16,16,16,float> acc[4][4];
    #pragma unroll
    for (int i = 0; i < 4; i++)
        #pragma unroll
        for (int j = 0; j < 4; j++)
            wmma::fill_fragment(acc[i][j], 0.0f);

    loadStage(0, 0);

    for (int kt = 0; kt < NT; kt++) {
        cp_wait<0>();
        __syncthreads();
        if (kt + 1 < NT) loadStage((kt + 1) & 1, kt + 1);

        const __half* as = As(kt & 1);
        const __half* bs = Bs(kt & 1);
        #pragma unroll
        for (int kk = 0; kk < BKH; kk += 16) {
            wmma::fragment<wmma::matrix_b,16,16,16,__half,wmma::col_major> bf[4];
            #pragma unroll
            for (int j = 0; j < 4; j++)
                wmma::load_matrix_sync(bf[j], bs + (wn*64 + j*16) * LDH + kk, LDH);
            #pragma unroll
            for (int i = 0; i < 4; i++) {
                wmma::fragment<wmma::matrix_a,16,16,16,__half,wmma::row_major> af;
                wmma::load_matrix_sync(af, as + (wm*64 + i*16) * LDH + kk, LDH);
                #pragma unroll
                for (int j = 0; j < 4; j++)
                    wmma::mma_sync(acc[i][j], af, bf[j], acc[i][j]);
            }
        }
    }
    __syncthreads();

    float* wstg = (float*)smh + warp * 352;
    #pragma unroll
    for (int i = 0; i < 4; i++) {
        #pragma unroll
        for (int j = 0; j < 4; j++) {
            wmma::store_matrix_sync(wstg, acc[i][j], 20, wmma::mem_row_major);
            __syncwarp();
            int r0 = rowBase + wm*64 + i*16;
            int c0 = colBase + wn*64 + j*16;
            int r  = lane >> 1;
            int cc = (lane & 1) * 8;
            float o[8];
            #pragma unroll
            for (int t = 0; t < 8; t++)
                o[t] = wstg[r*20 + cc + t] + __ldg(&bias[c0 + cc + t]);
            if (halfOut) {
                __half h[8];
                #pragma unroll
                for (int t = 0; t < 8; t++) h[t] = __float2half_rn(o[t]);
                *(uint4*)&((__half*)C)[(size_t)(r0 + r) * N + c0 + cc] = *(uint4*)h;
            } else {
                *(float4*)&((float*)C)[(size_t)(r0 + r) * N + c0 + cc]     = *(float4*)&o[0];
                *(float4*)&((float*)C)[(size_t)(r0 + r) * N + c0 + cc + 4] = *(float4*)&o[4];
            }
            __syncwarp();
        }
    }
}

// ---------------------------------------------------------------------------
// Block-local attention, fp16 operands / fp32 softmax. One CTA per window,
// 512 threads. Softmax: single smem read pass into registers; hybrid exp
// (even cols MUFU __expf, odd cols FMA-pipe polynomial) to break the MUFU
// throughput ceiling (67M EX2 ~= 0.5/cyc/SM was the whole kernel's bound).
// ---------------------------------------------------------------------------
#define ATTN_SMEM 186368

__global__ __launch_bounds__(512) void attn_kernel(
    const __half* __restrict__ q, const __half* __restrict__ k,
    const __half* __restrict__ v, __half* __restrict__ o,
    float* __restrict__ attnp)
{
    extern __shared__ char smraw[];
    __half* Ks = (__half*)smraw;
    __half* Vs = (__half*)(smraw + 36864);
    __half* Qs = (__half*)(smraw + 73728);
    float*  Ss = (float*) (smraw + 82944);
    __half* Ps = (__half*)(smraw + 150528);

    const int tid  = threadIdx.x;
    const int warp = tid >> 5;
    const int wm = warp >> 2;
    const int wn = warp & 3;

    const int bhw = blockIdx.x;
    const int w = bhw & 15;
    const int h = (bhw >> 4) & 15;
    const int b = bhw >> 8;

    const size_t tokBase = (size_t)b * SEQ + (size_t)w * BLKT;
    const int    colBase = h * HDIM;

    const __half* Kg = k + tokBase * DIMC + colBase;
    const __half* Vg = v + tokBase * DIMC + colBase;
    const __half* Qg = q + tokBase * DIMC + colBase;

    #pragma unroll
    for (int j = 0; j < 4; j++) {
        int i = tid + j * 512;
        int r = i >> 3, u = (i & 7) * 8;
        cp_async16(&Ks[r*LDH + u], Kg + (size_t)r * DIMC + u);
        cp_async16(&Vs[r*LDH + u], Vg + (size_t)r * DIMC + u);
    }
    {
        int r = tid >> 3, u = (tid & 7) * 8;
        cp_async16(&Qs[r*LDH + u], Qg + (size_t)r * DIMC + u);
    }
    cp_commit();
    cp_wait<0>();
    __syncthreads();

    for (int qc = 0; qc < 4; qc++) {
        // ---- S = Q @ K^T ----
        {
            wmma::fragment<wmma::accumulator,16,16,16,float> sacc[4];
            #pragma unroll
            for (int j = 0; j < 4; j++) wmma::fill_fragment(sacc[j], 0.0f);
            #pragma unroll
            for (int d0 = 0; d0 < HDIM; d0 += 16) {
                wmma::fragment<wmma::matrix_a,16,16,16,__half,wmma::row_major> af;
                wmma::load_matrix_sync(af, Qs + (wm*16)*LDH + d0, LDH);
                #pragma unroll
                for (int j = 0; j < 4; j++) {
                    wmma::fragment<wmma::matrix_b,16,16,16,__half,wmma::col_major> bf;
                    wmma::load_matrix_sync(bf, Ks + (size_t)(wn*64 + j*16)*LDH + d0, LDH);
                    wmma::mma_sync(sacc[j], af, bf, sacc[j]);
                }
            }
            #pragma unroll
            for (int j = 0; j < 4; j++)
                wmma::store_matrix_sync(Ss + (wm*16)*SLD + wn*64 + j*16, sacc[j],
                                        SLD, wmma::mem_row_major);
        }
        __syncthreads();

        if (qc < 3) {
            const __half* Qn = Qg + (size_t)(qc + 1) * QCH * DIMC;
            int r = tid >> 3, u = (tid & 7) * 8;
            cp_async16(&Qs[r*LDH + u], Qn + (size_t)r * DIMC + u);
            cp_commit();
        }

        // ---- softmax: regs + hybrid exp, write attn f32 + P f16 ----
        {
            const int row  = tid >> 3;
            const int part = tid & 7;
            const float* srow = Ss + row * SLD;
            __half* prow = Ps + row * PLD;
            float rg[32];
            #pragma unroll
            for (int j = 0; j < 32; j++) rg[j] = srow[j*8 + part];
            float mx = rg[0];
            #pragma unroll
            for (int j = 1; j < 32; j++) mx = fmaxf(mx, rg[j]);
            mx = fmaxf(mx, __shfl_xor_sync(0xffffffffu, mx, 1));
            mx = fmaxf(mx, __shfl_xor_sync(0xffffffffu, mx, 2));
            mx = fmaxf(mx, __shfl_xor_sync(0xffffffffu, mx, 4));
            float sum = 0.0f;
            #pragma unroll
            for (int j = 0; j < 32; j++) {
                float vv = (rg[j] - mx) * ATTN_SCALE;
                float e = (j & 1) ? exp_poly(vv) : __expf(vv);
                rg[j] = e;
                sum += e;
            }
            sum += __shfl_xor_sync(0xffffffffu, sum, 1);
            sum += __shfl_xor_sync(0xffffffffu, sum, 2);
            sum += __shfl_xor_sync(0xffffffffu, sum, 4);
            const float inv = 1.0f / sum;
            float* arow = attnp + ((((size_t)b*NHEAD + h)*NWIN + w)*BLKT
                                   + qc*QCH + row) * BLKT;
            #pragma unroll
            for (int j = 0; j < 32; j++) {
                float p = rg[j] * inv;
                __stcs(&arow[j*8 + part], p);
                prow[j*8 + part] = __float2half_rn(p);
            }
        }
        __syncthreads();

        // ---- O = P @ V ----
        {
            wmma::fragment<wmma::accumulator,16,16,16,float> oacc;
            wmma::fill_fragment(oacc, 0.0f);
            #pragma unroll
            for (int k0 = 0; k0 < BLKT; k0 += 16) {
                wmma::fragment<wmma::matrix_a,16,16,16,__half,wmma::row_major> af;
                wmma::load_matrix_sync(af, Ps + (wm*16)*PLD + k0, PLD);
                wmma::fragment<wmma::matrix_b,16,16,16,__half,wmma::row_major> bf;
                wmma::load_matrix_sync(bf, Vs + (size_t)k0*LDH + wn*16, LDH);
                wmma::mma_sync(oacc, af, bf, oacc);
            }
            float* wstg = Ss + warp * 352;
            wmma::store_matrix_sync(wstg, oacc, 16, wmma::mem_row_major);
            __syncwarp();
            const int lane = tid & 31;
            int r  = lane >> 1;
            int cc = (lane & 1) * 8;
            __half hv[8];
            #pragma unroll
            for (int t = 0; t < 8; t++)
                hv[t] = __float2half_rn(wstg[r*16 + cc + t]);
            __half* optr = o + (tokBase + (size_t)qc*QCH + wm*16 + r) * DIMC
                             + colBase + wn*16 + cc;
            *(uint4*)optr = *(uint4*)hv;
        }

        if (qc < 3) cp_wait<0>();
        __syncthreads();
    }
}

// ---------------------------------------------------------------------------
extern "C" void kernel_launch(void* const* d_in, const int* in_sizes, int n_in,
                              void* d_out, int out_size)
{
    const float* x  = (const float*)d_in[0];
    const float* Wq = (const float*)d_in[1];
    const float* bq = (const float*)d_in[2];
    const float* Wk = (const float*)d_in[3];
    const float* bk = (const float*)d_in[4];
    const float* Wv = (const float*)d_in[5];
    const float* bv = (const float*)d_in[6];
    const float* Wo = (const float*)d_in[7];
    const float* bo = (const float*)d_in[8];

    float* out = (float*)d_out;
    const size_t out_elems = (size_t)MTOK * DIMC;
    float* attnp = out + out_elems;

    __half* scratch = nullptr;
    cudaGetSymbolAddress((void**)&scratch, g_scratch_h);
    __half* xh  = scratch;
    __half* qh  = xh  + out_elems;
    __half* kh  = qh  + out_elems;
    __half* vh  = kh  + out_elems;
    __half* goh = vh  + out_elems;
    __half* wh  = goh + out_elems;
    const size_t wsz = (size_t)DIMC * DIMC;
    __half* whq = wh;
    __half* whk = wh + wsz;
    __half* whv = wh + 2*wsz;
    __half* who = wh + 3*wsz;

    {
        dim3 rg(256, 1, 5);
        conv_half_kernel<<<rg, 256>>>(
            (const float4*)x,  xh,
            (const float4*)Wq, whq,
            (const float4*)Wk, whk,
            (const float4*)Wv, whv,
            (const float4*)Wo, who);
    }

    const size_t gemm_smem = 2ull * 2 * BM * LDH * sizeof(__half);  // 73728
    cudaFuncSetAttribute(gemm3_f16, cudaFuncAttributeMaxDynamicSharedMemorySize, (int)gemm_smem);

    dim3 gg(DIMC / BN, MTOK / BM, 3);
    gemm3_f16<<<gg, 128, gemm_smem>>>(xh, whq, bq, qh, whk, bk, kh, whv, bv, vh, 1);

    cudaFuncSetAttribute(attn_kernel, cudaFuncAttributeMaxDynamicSharedMemorySize, ATTN_SMEM);
    attn_kernel<<<BATCH*NHEAD*NWIN, 512, ATTN_SMEM>>>(qh, kh, vh, goh, attnp);

    dim3 go_grid(DIMC / BN, MTOK / BM, 1);
    gemm3_f16<<<go_grid, 128, gemm_smem>>>(goh, who, bo, out, who, bo, out, who, bo, out, 0);
}

// round 11
// speedup vs baseline: 4.1511x; 1.0434x over previous
#include <cuda_runtime.h>
#include <cuda_fp16.h>
#include <mma.h>
#include <math.h>
#include <stdint.h>

using namespace nvcuda;

#define BATCH 4
#define SEQ   4096
#define DIMC  1024
#define NHEAD 16
#define HDIM  64
#define NWIN  16
#define BLKT  256
#define MTOK  (BATCH*SEQ)
#define ATTN_SCALE 0.125f

#define BM 128
#define BN 128
#define BKH 64
#define LDH 72           // half stride (144B rows, conflict-free LDSM)
#define NT  (DIMC / BKH)
#define PLDW 264         // P strip stride (halves)

// scratch (halves): xh, qh, kh, vh, goh (5 x 16M half) + 4 weights
__device__ __half g_scratch_h[5ull * MTOK * DIMC + 4ull * DIMC * DIMC];

// ---------------- helpers ----------------
__device__ __forceinline__ void cp_async16(void* smem, const void* gmem) {
    unsigned s = (unsigned)__cvta_generic_to_shared(smem);
    asm volatile("cp.async.cg.shared.global [%0], [%1], 16;\n" :: "r"(s), "l"(gmem));
}
__device__ __forceinline__ void cp_commit() {
    asm volatile("cp.async.commit_group;\n");
}
template<int N> __device__ __forceinline__ void cp_wait() {
    asm volatile("cp.async.wait_group %0;\n" :: "n"(N));
}
__device__ __forceinline__ float exp_poly(float v) {
    float t = v * 1.4426950408889634f;
    float fi = floorf(t);
    float f = t - fi;
    float p = 0.0001540353039338f;
    p = fmaf(p, f, 0.0013333558146428f);
    p = fmaf(p, f, 0.0096181291076285f);
    p = fmaf(p, f, 0.0555041086648216f);
    p = fmaf(p, f, 0.2402265069591007f);
    p = fmaf(p, f, 0.6931471805599453f);
    p = fmaf(p, f, 1.0f);
    int ei = (int)fi;
    ei = (ei < -126) ? -126 : ei;
    return p * __int_as_float((ei + 127) << 23);
}
__device__ __forceinline__ void ldsm_x4(uint32_t& r0, uint32_t& r1,
                                        uint32_t& r2, uint32_t& r3, uint32_t a) {
    asm volatile("ldmatrix.sync.aligned.m8n8.x4.shared.b16 {%0,%1,%2,%3}, [%4];"
                 : "=r"(r0), "=r"(r1), "=r"(r2), "=r"(r3) : "r"(a));
}
__device__ __forceinline__ void mma16816(float* c, const uint32_t* a,
                                         uint32_t b0, uint32_t b1) {
    asm volatile(
        "mma.sync.aligned.m16n8k16.row.col.f32.f16.f16.f32 "
        "{%0,%1,%2,%3}, {%4,%5,%6,%7}, {%8,%9}, {%0,%1,%2,%3};"
        : "+f"(c[0]), "+f"(c[1]), "+f"(c[2]), "+f"(c[3])
        : "r"(a[0]), "r"(a[1]), "r"(a[2]), "r"(a[3]), "r"(b0), "r"(b1));
}

// ---------------------------------------------------------------------------
// f32 -> f16 conversion prepass (unchanged)
// ---------------------------------------------------------------------------
__global__ void conv_half_kernel(
    const float4* __restrict__ x,  __half* __restrict__ xh,
    const float4* __restrict__ w0, __half* __restrict__ w0h,
    const float4* __restrict__ w1, __half* __restrict__ w1h,
    const float4* __restrict__ w2, __half* __restrict__ w2h,
    const float4* __restrict__ w3, __half* __restrict__ w3h)
{
    const float4* src; __half* dst; int n4;
    switch (blockIdx.z) {
        case 0:  src = x;  dst = xh;  n4 = MTOK * DIMC / 4; break;
        case 1:  src = w0; dst = w0h; n4 = DIMC * DIMC / 4; break;
        case 2:  src = w1; dst = w1h; n4 = DIMC * DIMC / 4; break;
        case 3:  src = w2; dst = w2h; n4 = DIMC * DIMC / 4; break;
        default: src = w3; dst = w3h; n4 = DIMC * DIMC / 4; break;
    }
    for (int i = blockIdx.x * blockDim.x + threadIdx.x; i < n4;
         i += gridDim.x * blockDim.x) {
        float4 v = src[i];
        __half2 a = __floats2half2_rn(v.x, v.y);
        __half2 b = __floats2half2_rn(v.z, v.w);
        uint2 o;
        o.x = *(const unsigned*)&a;
        o.y = *(const unsigned*)&b;
        *(uint2*)(dst + 4ull * i) = o;
    }
}

// ---------------------------------------------------------------------------
// fp16 GEMM (unchanged from R9/R10 best)
// ---------------------------------------------------------------------------
__global__ __launch_bounds__(128, 3) void gemm3_f16(
    const __half* __restrict__ A,
    const __half* __restrict__ W0, const float* __restrict__ b0, void* __restrict__ C0,
    const __half* __restrict__ W1, const float* __restrict__ b1, void* __restrict__ C1,
    const __half* __restrict__ W2, const float* __restrict__ b2, void* __restrict__ C2,
    int halfOut)
{
    extern __shared__ __half smh[];
    const __half* Bw; const float* bias; void* C;
    if (blockIdx.z == 0)      { Bw = W0; bias = b0; C = C0; }
    else if (blockIdx.z == 1) { Bw = W1; bias = b1; C = C1; }
    else                      { Bw = W2; bias = b2; C = C2; }

    const int K = DIMC, N = DIMC;
    const int tid  = threadIdx.x;
    const int warp = tid >> 5;
    const int lane = tid & 31;
    const int wm = warp & 1;
    const int wn = warp >> 1;
    const int rowBase = blockIdx.y * BM;
    const int colBase = blockIdx.x * BN;

    const int stageH = BM * LDH;
    auto As = [&](int s) { return smh + (size_t)s * 2 * stageH; };
    auto Bs = [&](int s) { return smh + (size_t)s * 2 * stageH + stageH; };

    const int lr = tid >> 3;
    const int lc = (tid & 7) * 8;

    auto loadStage = [&](int s, int kt) {
        __half* as = As(s); __half* bs = Bs(s);
        int k0 = kt * BKH;
        #pragma unroll
        for (int j = 0; j < 8; j++) {
            int r = lr + j * 16;
            cp_async16(&as[r * LDH + lc], &A [(size_t)(rowBase + r) * K + k0 + lc]);
            cp_async16(&bs[r * LDH + lc], &Bw[(size_t)(colBase + r) * K + k0 + lc]);
        }
        cp_commit();
    };

    wmma::fragment<wmma::accumulator,16,16,16,float> acc[4][4];
    #pragma unroll
    for (int i = 0; i < 4; i++)
        #pragma unroll
        for (int j = 0; j < 4; j++)
            wmma::fill_fragment(acc[i][j], 0.0f);

    loadStage(0, 0);

    for (int kt = 0; kt < NT; kt++) {
        cp_wait<0>();
        __syncthreads();
        if (kt + 1 < NT) loadStage((kt + 1) & 1, kt + 1);

        const __half* as = As(kt & 1);
        const __half* bs = Bs(kt & 1);
        #pragma unroll
        for (int kk = 0; kk < BKH; kk += 16) {
            wmma::fragment<wmma::matrix_b,16,16,16,__half,wmma::col_major> bf[4];
            #pragma unroll
            for (int j = 0; j < 4; j++)
                wmma::load_matrix_sync(bf[j], bs + (wn*64 + j*16) * LDH + kk, LDH);
            #pragma unroll
            for (int i = 0; i < 4; i++) {
                wmma::fragment<wmma::matrix_a,16,16,16,__half,wmma::row_major> af;
                wmma::load_matrix_sync(af, as + (wm*64 + i*16) * LDH + kk, LDH);
                #pragma unroll
                for (int j = 0; j < 4; j++)
                    wmma::mma_sync(acc[i][j], af, bf[j], acc[i][j]);
            }
        }
    }
    __syncthreads();

    float* wstg = (float*)smh + warp * 352;
    #pragma unroll
    for (int i = 0; i < 4; i++) {
        #pragma unroll
        for (int j = 0; j < 4; j++) {
            wmma::store_matrix_sync(wstg, acc[i][j], 20, wmma::mem_row_major);
            __syncwarp();
            int r0 = rowBase + wm*64 + i*16;
            int c0 = colBase + wn*64 + j*16;
            int r  = lane >> 1;
            int cc = (lane & 1) * 8;
            float o[8];
            #pragma unroll
            for (int t = 0; t < 8; t++)
                o[t] = wstg[r*20 + cc + t] + __ldg(&bias[c0 + cc + t]);
            if (halfOut) {
                __half h[8];
                #pragma unroll
                for (int t = 0; t < 8; t++) h[t] = __float2half_rn(o[t]);
                *(uint4*)&((__half*)C)[(size_t)(r0 + r) * N + c0 + cc] = *(uint4*)h;
            } else {
                *(float4*)&((float*)C)[(size_t)(r0 + r) * N + c0 + cc]     = *(float4*)&o[0];
                *(float4*)&((float*)C)[(size_t)(r0 + r) * N + c0 + cc + 4] = *(float4*)&o[4];
            }
            __syncwarp();
        }
    }
}

// ---------------------------------------------------------------------------
// Attention v2: register-resident softmax, no inner barriers.
// CTA = 128 q-rows of one window (2 CTAs/window), 256 threads (8 warps).
// Warp owns 16 q-rows x 256 cols: S in 128 regs via mma.m16n8k16;
// softmax via quad shuffles on the mma C layout; attn written from regs;
// P (fp16) to warp-private smem; PV via wmma. Single __syncthreads total.
// smem: Ks 36864 | Vs 36864 | Qs 18432 | Ps 8*8448  = 159744 bytes
// ---------------------------------------------------------------------------
#define ATTN_SMEM2 159744

__global__ __launch_bounds__(256, 1) void attn_kernel(
    const __half* __restrict__ q, const __half* __restrict__ k,
    const __half* __restrict__ v, __half* __restrict__ o,
    float* __restrict__ attnp)
{
    extern __shared__ char smraw[];
    __half* Ks = (__half*)smraw;
    __half* Vs = (__half*)(smraw + 36864);
    __half* Qs = (__half*)(smraw + 73728);
    __half* Ps = (__half*)(smraw + 92160);

    const int tid  = threadIdx.x;
    const int warp = tid >> 5;
    const int lane = tid & 31;
    const int g    = lane >> 2;      // mma row group
    const int tg   = lane & 3;       // thread-in-group (col pairs)

    const int idx = blockIdx.x;
    const int qh  = idx & 1;         // which 128-row half
    const int bhw = idx >> 1;
    const int w = bhw & 15;
    const int h = (bhw >> 4) & 15;
    const int b = bhw >> 8;

    const size_t tokBase = (size_t)b * SEQ + (size_t)w * BLKT;
    const int    colBase = h * HDIM;
    const int    qrow0   = qh * 128;

    const __half* Kg = k + tokBase * DIMC + colBase;
    const __half* Vg = v + tokBase * DIMC + colBase;
    const __half* Qg = q + (tokBase + qrow0) * DIMC + colBase;

    // K,V: 256 rows x 8 chunks; Q: 128 rows x 8 chunks. 256 threads.
    #pragma unroll
    for (int j = 0; j < 8; j++) {
        int i = tid + j * 256;
        int r = i >> 3, u = (i & 7) * 8;
        cp_async16(&Ks[r*LDH + u], Kg + (size_t)r * DIMC + u);
        cp_async16(&Vs[r*LDH + u], Vg + (size_t)r * DIMC + u);
    }
    #pragma unroll
    for (int j = 0; j < 4; j++) {
        int i = tid + j * 256;
        int r = i >> 3, u = (i & 7) * 8;
        cp_async16(&Qs[r*LDH + u], Qg + (size_t)r * DIMC + u);
    }
    cp_commit();
    cp_wait<0>();
    __syncthreads();          // the only CTA barrier

    // ---- A fragments: warp's 16 Q rows, 4 k-tiles (HDIM=64) ----
    uint32_t qbase = (uint32_t)__cvta_generic_to_shared(Qs)
                   + ((warp*16 + (lane & 15)) * LDH + ((lane & 16) ? 8 : 0)) * 2;
    uint32_t Af[4][4];
    #pragma unroll
    for (int kt = 0; kt < 4; kt++)
        ldsm_x4(Af[kt][0], Af[kt][1], Af[kt][2], Af[kt][3], qbase + kt * 32);

    // ---- S = Q @ K^T : 32 n-tiles x 4 k-steps ----
    float acc[32][4];
    #pragma unroll
    for (int j = 0; j < 32; j++)
        #pragma unroll
        for (int c = 0; c < 4; c++) acc[j][c] = 0.0f;

    uint32_t kbase = (uint32_t)__cvta_generic_to_shared(Ks)
                   + (((lane & 7) + ((lane & 16) ? 8 : 0)) * LDH
                      + ((lane & 8) ? 8 : 0)) * 2;
    #pragma unroll
    for (int j2 = 0; j2 < 16; j2++) {          // pairs of n-tiles (16 tokens)
        uint32_t kb = kbase + j2 * 16 * LDH * 2;
        #pragma unroll
        for (int kt = 0; kt < 4; kt++) {
            uint32_t b0, b1, b2, b3;
            ldsm_x4(b0, b1, b2, b3, kb + kt * 32);
            mma16816(acc[2*j2],     Af[kt], b0, b1);
            mma16816(acc[2*j2 + 1], Af[kt], b2, b3);
        }
    }

    // ---- register softmax (rows g and g+8 of warp strip) ----
    float mx0 = -1e30f, mx1 = -1e30f;
    #pragma unroll
    for (int j = 0; j < 32; j++) {
        mx0 = fmaxf(mx0, fmaxf(acc[j][0], acc[j][1]));
        mx1 = fmaxf(mx1, fmaxf(acc[j][2], acc[j][3]));
    }
    mx0 = fmaxf(mx0, __shfl_xor_sync(0xffffffffu, mx0, 1));
    mx0 = fmaxf(mx0, __shfl_xor_sync(0xffffffffu, mx0, 2));
    mx1 = fmaxf(mx1, __shfl_xor_sync(0xffffffffu, mx1, 1));
    mx1 = fmaxf(mx1, __shfl_xor_sync(0xffffffffu, mx1, 2));

    float sum0 = 0.0f, sum1 = 0.0f;
    #pragma unroll
    for (int j = 0; j < 32; j++) {
        float e0, e1, e2, e3;
        if (j & 1) {
            e0 = exp_poly((acc[j][0] - mx0) * ATTN_SCALE);
            e1 = exp_poly((acc[j][1] - mx0) * ATTN_SCALE);
            e2 = exp_poly((acc[j][2] - mx1) * ATTN_SCALE);
            e3 = exp_poly((acc[j][3] - mx1) * ATTN_SCALE);
        } else {
            e0 = __expf((acc[j][0] - mx0) * ATTN_SCALE);
            e1 = __expf((acc[j][1] - mx0) * ATTN_SCALE);
            e2 = __expf((acc[j][2] - mx1) * ATTN_SCALE);
            e3 = __expf((acc[j][3] - mx1) * ATTN_SCALE);
        }
        acc[j][0] = e0; acc[j][1] = e1; acc[j][2] = e2; acc[j][3] = e3;
        sum0 += e0 + e1;
        sum1 += e2 + e3;
    }
    sum0 += __shfl_xor_sync(0xffffffffu, sum0, 1);
    sum0 += __shfl_xor_sync(0xffffffffu, sum0, 2);
    sum1 += __shfl_xor_sync(0xffffffffu, sum1, 1);
    sum1 += __shfl_xor_sync(0xffffffffu, sum1, 2);
    const float inv0 = 1.0f / sum0;
    const float inv1 = 1.0f / sum1;

    // ---- write attn (f32, from regs) + P (f16, warp-private smem) ----
    {
        const int lrow0 = warp*16 + g;          // CTA-local rows
        float* a0 = attnp + ((((size_t)b*NHEAD + h)*NWIN + w)*BLKT
                             + qrow0 + lrow0) * BLKT + tg*2;
        float* a1 = a0 + 8 * BLKT;              // row +8
        __half* p0 = Ps + (size_t)warp*4224 + (size_t)g     * PLDW + tg*2;
        __half* p1 = p0 + 8 * PLDW;
        #pragma unroll
        for (int j = 0; j < 32; j++) {
            float v0 = acc[j][0] * inv0, v1 = acc[j][1] * inv0;
            float v2 = acc[j][2] * inv1, v3 = acc[j][3] * inv1;
            float2 f0 = {v0, v1}, f1 = {v2, v3};
            __stcs((float2*)(a0 + j*8), f0);
            __stcs((float2*)(a1 + j*8), f1);
            __half2 h0 = __floats2half2_rn(v0, v1);
            __half2 h1 = __floats2half2_rn(v2, v3);
            *(__half2*)(p0 + j*8) = h0;
            *(__half2*)(p1 + j*8) = h1;
        }
    }
    __syncwarp();

    // ---- O = P @ V : warp-private P, shared V, wmma ----
    {
        __half* Pw = Ps + (size_t)warp * 4224;
        wmma::fragment<wmma::accumulator,16,16,16,float> oacc[4];
        #pragma unroll
        for (int t = 0; t < 4; t++) wmma::fill_fragment(oacc[t], 0.0f);
        #pragma unroll
        for (int k0 = 0; k0 < BLKT; k0 += 16) {
            wmma::fragment<wmma::matrix_a,16,16,16,__half,wmma::row_major> af;
            wmma::load_matrix_sync(af, Pw + k0, PLDW);
            #pragma unroll
            for (int t = 0; t < 4; t++) {
                wmma::fragment<wmma::matrix_b,16,16,16,__half,wmma::row_major> bf;
                wmma::load_matrix_sync(bf, Vs + (size_t)k0*LDH + t*16, LDH);
                wmma::mma_sync(oacc[t], af, bf, oacc[t]);
            }
        }
        __syncwarp();
        float* wstg = (float*)(smraw + 92160 + (size_t)warp * 8448);
        #pragma unroll
        for (int t = 0; t < 4; t++) {
            wmma::store_matrix_sync(wstg, oacc[t], 16, wmma::mem_row_major);
            __syncwarp();
            int r  = lane >> 1;
            int cc = (lane & 1) * 8;
            __half hv[8];
            #pragma unroll
            for (int u = 0; u < 8; u++)
                hv[u] = __float2half_rn(wstg[r*16 + cc + u]);
            __half* optr = o + (tokBase + qrow0 + warp*16 + r) * DIMC
                             + colBase + t*16 + cc;
            *(uint4*)optr = *(uint4*)hv;
            __syncwarp();
        }
    }
}

// ---------------------------------------------------------------------------
extern "C" void kernel_launch(void* const* d_in, const int* in_sizes, int n_in,
                              void* d_out, int out_size)
{
    const float* x  = (const float*)d_in[0];
    const float* Wq = (const float*)d_in[1];
    const float* bq = (const float*)d_in[2];
    const float* Wk = (const float*)d_in[3];
    const float* bk = (const float*)d_in[4];
    const float* Wv = (const float*)d_in[5];
    const float* bv = (const float*)d_in[6];
    const float* Wo = (const float*)d_in[7];
    const float* bo = (const float*)d_in[8];

    float* out = (float*)d_out;
    const size_t out_elems = (size_t)MTOK * DIMC;
    float* attnp = out + out_elems;

    __half* scratch = nullptr;
    cudaGetSymbolAddress((void**)&scratch, g_scratch_h);
    __half* xh  = scratch;
    __half* qh  = xh  + out_elems;
    __half* kh  = qh  + out_elems;
    __half* vh  = kh  + out_elems;
    __half* goh = vh  + out_elems;
    __half* wh  = goh + out_elems;
    const size_t wsz = (size_t)DIMC * DIMC;
    __half* whq = wh;
    __half* whk = wh + wsz;
    __half* whv = wh + 2*wsz;
    __half* who = wh + 3*wsz;

    {
        dim3 rg(256, 1, 5);
        conv_half_kernel<<<rg, 256>>>(
            (const float4*)x,  xh,
            (const float4*)Wq, whq,
            (const float4*)Wk, whk,
            (const float4*)Wv, whv,
            (const float4*)Wo, who);
    }

    const size_t gemm_smem = 2ull * 2 * BM * LDH * sizeof(__half);  // 73728
    cudaFuncSetAttribute(gemm3_f16, cudaFuncAttributeMaxDynamicSharedMemorySize, (int)gemm_smem);

    dim3 gg(DIMC / BN, MTOK / BM, 3);
    gemm3_f16<<<gg, 128, gemm_smem>>>(xh, whq, bq, qh, whk, bk, kh, whv, bv, vh, 1);

    cudaFuncSetAttribute(attn_kernel, cudaFuncAttributeMaxDynamicSharedMemorySize, ATTN_SMEM2);
    attn_kernel<<<BATCH*NHEAD*NWIN*2, 256, ATTN_SMEM2>>>(qh, kh, vh, goh, attnp);

    dim3 go_grid(DIMC / BN, MTOK / BM, 1);
    gemm3_f16<<<go_grid, 128, gemm_smem>>>(goh, who, bo, out, who, bo, out, who, bo, out, 0);
}